// round 5
// baseline (speedup 1.0000x reference)
#include <cuda_runtime.h>
#include <cstddef>

// Problem dims
#define T_STEPS 16
#define B_DIM   64
#define S_DIM   512
#define H_DIM   2048
#define A_DIM   32
#define MROWS   (T_STEPS * B_DIM)          // 1024
#define NELEM   ((size_t)MROWS * H_DIM)    // 2,097,152
#define MBIG    (T_STEPS * MROWS)          // 16384

// Output layout: concat of (value, action, m1, m2, m_act, m_crit), fp32
#define OFF_VALUE  0
#define OFF_ACTION 1024
#define OFF_M1     33792
#define OFF_M2     2130944
#define OFF_MACT   4228096
#define OFF_MCRIT  4260864

// Scratch (device globals: allocation-free per harness rules)
__device__ float g_cur1[MROWS * H_DIM];                    // 8 MB
__device__ float g_S1[(size_t)T_STEPS * MROWS * H_DIM];    // 128 MB
__device__ float g_H[(size_t)T_STEPS * MROWS * H_DIM];     // 128 MB
__device__ float g_S2[MROWS * H_DIM];                      // 8 MB

// ---------------------------------------------------------------------------
// NT SGEMM (single-accumulator, strictly ascending k) — BIT-EXACT for cur1,
// proven by m1 rel_err = 0 across rounds 3-4. DO NOT TOUCH.
// ---------------------------------------------------------------------------
__global__ __launch_bounds__(256) void sgemm_nt(
    const float* __restrict__ A, const float* __restrict__ B,
    const float* __restrict__ bias, float* __restrict__ C,
    int M, int N, int K)
{
    __shared__ float As[8][128];
    __shared__ float Bs[8][128];

    const int tid = threadIdx.x;
    const int bm = blockIdx.y * 128;
    const int bn = blockIdx.x * 128;

    const int lrow = tid >> 1;
    const int lcol = (tid & 1) * 4;

    const int tx = tid & 15;
    const int ty = tid >> 4;

    float acc[8][8];
#pragma unroll
    for (int i = 0; i < 8; i++)
#pragma unroll
        for (int j = 0; j < 8; j++) acc[i][j] = 0.0f;

    const float* Aptr = A + (size_t)(bm + lrow) * K + lcol;
    const float* Bptr = B + (size_t)(bn + lrow) * K + lcol;

    for (int k0 = 0; k0 < K; k0 += 8) {
        float4 a4 = *(const float4*)(Aptr + k0);
        float4 b4 = *(const float4*)(Bptr + k0);
        As[lcol + 0][lrow] = a4.x; As[lcol + 1][lrow] = a4.y;
        As[lcol + 2][lrow] = a4.z; As[lcol + 3][lrow] = a4.w;
        Bs[lcol + 0][lrow] = b4.x; Bs[lcol + 1][lrow] = b4.y;
        Bs[lcol + 2][lrow] = b4.z; Bs[lcol + 3][lrow] = b4.w;
        __syncthreads();

#pragma unroll
        for (int k = 0; k < 8; k++) {
            float ar[8], br[8];
            float4 t;
            t = *(const float4*)&As[k][ty * 8];     ar[0]=t.x; ar[1]=t.y; ar[2]=t.z; ar[3]=t.w;
            t = *(const float4*)&As[k][ty * 8 + 4]; ar[4]=t.x; ar[5]=t.y; ar[6]=t.z; ar[7]=t.w;
            t = *(const float4*)&Bs[k][tx * 8];     br[0]=t.x; br[1]=t.y; br[2]=t.z; br[3]=t.w;
            t = *(const float4*)&Bs[k][tx * 8 + 4]; br[4]=t.x; br[5]=t.y; br[6]=t.z; br[7]=t.w;
#pragma unroll
            for (int i = 0; i < 8; i++)
#pragma unroll
                for (int j = 0; j < 8; j++)
                    acc[i][j] = fmaf(ar[i], br[j], acc[i][j]);
        }
        __syncthreads();
    }

    const int row0 = bm + ty * 8;
    const int col0 = bn + tx * 8;
#pragma unroll
    for (int i = 0; i < 8; i++) {
#pragma unroll
        for (int jv = 0; jv < 8; jv += 4) {
            float4 v;
            v.x = __fadd_rn(acc[i][jv + 0], bias[col0 + jv + 0]);
            v.y = __fadd_rn(acc[i][jv + 1], bias[col0 + jv + 1]);
            v.z = __fadd_rn(acc[i][jv + 2], bias[col0 + jv + 2]);
            v.w = __fadd_rn(acc[i][jv + 3], bias[col0 + jv + 3]);
            *(float4*)(C + (size_t)(row0 + i) * N + col0 + jv) = v;
        }
    }
}

// ---------------------------------------------------------------------------
// 4-way K-sliced NT SGEMM (sliced1x4 hypothesis):
// per element: P_s = ascending FMA chain over k in [s*K/4, (s+1)*K/4),
//              C = (((P0+P1)+P2)+P3) + bias.
// Implemented with 2 accumulator planes: accumulate each slice into B,
// fold A = A + B serially — reproduces the serial merge exactly.
// BM=128, BN=64, BK=16, TM=8, TN=4, 256 threads.
// ---------------------------------------------------------------------------
#define SPLIT_TILE_LOOP(KSTART, KEND, ACC)                                    \
    for (int k0 = (KSTART); k0 < (KEND); k0 += 16) {                          \
        {                                                                     \
            float4 a4 = *(const float4*)(Aptr + k0);                          \
            float4 a4b = *(const float4*)(Aptr + k0 + 4);                     \
            As[ak + 0][arow] = a4.x;  As[ak + 1][arow] = a4.y;                \
            As[ak + 2][arow] = a4.z;  As[ak + 3][arow] = a4.w;                \
            As[ak + 4][arow] = a4b.x; As[ak + 5][arow] = a4b.y;               \
            As[ak + 6][arow] = a4b.z; As[ak + 7][arow] = a4b.w;               \
            float4 b4 = *(const float4*)(Bptr + k0);                          \
            Bs[bk + 0][brow] = b4.x; Bs[bk + 1][brow] = b4.y;                 \
            Bs[bk + 2][brow] = b4.z; Bs[bk + 3][brow] = b4.w;                 \
        }                                                                     \
        __syncthreads();                                                      \
        _Pragma("unroll")                                                     \
        for (int k = 0; k < 16; k++) {                                        \
            float ar[8];                                                      \
            float4 t;                                                         \
            t = *(const float4*)&As[k][ty * 8];                               \
            ar[0]=t.x; ar[1]=t.y; ar[2]=t.z; ar[3]=t.w;                       \
            t = *(const float4*)&As[k][ty * 8 + 4];                           \
            ar[4]=t.x; ar[5]=t.y; ar[6]=t.z; ar[7]=t.w;                       \
            float4 b4 = *(const float4*)&Bs[k][tx * 4];                       \
            float br[4] = {b4.x, b4.y, b4.z, b4.w};                           \
            _Pragma("unroll")                                                 \
            for (int i = 0; i < 8; i++)                                       \
                _Pragma("unroll")                                             \
                for (int j = 0; j < 4; j++)                                   \
                    ACC[i][j] = fmaf(ar[i], br[j], ACC[i][j]);                \
        }                                                                     \
        __syncthreads();                                                      \
    }

__global__ __launch_bounds__(256) void sgemm_split4_nt(
    const float* __restrict__ A, const float* __restrict__ B,
    const float* __restrict__ bias, float* __restrict__ C,
    int M, int N, int K)
{
    __shared__ float As[16][128];
    __shared__ float Bs[16][64];

    const int tid = threadIdx.x;
    const int bm = blockIdx.y * 128;
    const int bn = blockIdx.x * 64;

    const int arow = tid >> 1;          // 0..127
    const int ak   = (tid & 1) * 8;     // 0 or 8
    const int brow = tid >> 2;          // 0..63
    const int bk   = (tid & 3) * 4;     // 0,4,8,12

    const int ty = tid >> 4;            // rows ty*8
    const int tx = tid & 15;            // cols tx*4

    float accA[8][4], accB[8][4];
#pragma unroll
    for (int i = 0; i < 8; i++)
#pragma unroll
        for (int j = 0; j < 4; j++) accA[i][j] = 0.0f;

    const float* Aptr = A + (size_t)(bm + arow) * K + ak;
    const float* Bptr = B + (size_t)(bn + brow) * K + bk;

    const int Kq = K >> 2;   // slice length

    // slice 0 -> accA
    SPLIT_TILE_LOOP(0, Kq, accA)

    // slices 1..3 -> accB, fold serially: A = A + B
#pragma unroll 1
    for (int s = 1; s < 4; s++) {
#pragma unroll
        for (int i = 0; i < 8; i++)
#pragma unroll
            for (int j = 0; j < 4; j++) accB[i][j] = 0.0f;
        const int ks = s * Kq;
        const int ke = ks + Kq;
        SPLIT_TILE_LOOP(ks, ke, accB)
#pragma unroll
        for (int i = 0; i < 8; i++)
#pragma unroll
            for (int j = 0; j < 4; j++)
                accA[i][j] = __fadd_rn(accA[i][j], accB[i][j]);
    }

    const int row0 = bm + ty * 8;
    const int col0 = bn + tx * 4;
#pragma unroll
    for (int i = 0; i < 8; i++) {
        float4 v;
        v.x = __fadd_rn(accA[i][0], bias[col0 + 0]);
        v.y = __fadd_rn(accA[i][1], bias[col0 + 1]);
        v.z = __fadd_rn(accA[i][2], bias[col0 + 2]);
        v.w = __fadd_rn(accA[i][3], bias[col0 + 3]);
        *(float4*)(C + (size_t)(row0 + i) * N + col0) = v;
    }
}

// ---------------------------------------------------------------------------
// m1 scan (BIT-EXACT — do not touch)
// ---------------------------------------------------------------------------
__global__ void k_scan1(const float* __restrict__ cur1,
                        const float* __restrict__ mem1,
                        const float* __restrict__ beta1p,
                        float* __restrict__ m1_out,
                        float* __restrict__ S1)
{
    size_t e = (size_t)blockIdx.x * blockDim.x + threadIdx.x;
    if (e >= NELEM) return;
    const float beta = *beta1p;
    const float c = cur1[e];
    float m = mem1[e];
#pragma unroll
    for (int k = 0; k < T_STEPS; k++) {
        float reset = (m > 1.0f) ? 1.0f : 0.0f;
        m = __fsub_rn(fmaf(beta, m, c), reset);
        S1[(size_t)k * NELEM + e] = (m > 1.0f) ? 1.0f : 0.0f;
    }
    m1_out[e] = m;
}

// ---------------------------------------------------------------------------
// m2 scan over precomputed h_k (b2 folded in by the GEMM), FMA form.
// ---------------------------------------------------------------------------
__global__ void k_scan2(const float* __restrict__ Hbuf,
                        const float* __restrict__ mem2,
                        const float* __restrict__ beta2p,
                        float* __restrict__ m2_out,
                        float* __restrict__ S2)
{
    size_t e = (size_t)blockIdx.x * blockDim.x + threadIdx.x;
    if (e >= NELEM) return;
    const float beta = *beta2p;
    float m = mem2[e];
#pragma unroll
    for (int k = 0; k < T_STEPS; k++) {
        float h = Hbuf[(size_t)k * NELEM + e];
        float reset = (m > 1.0f) ? 1.0f : 0.0f;
        m = __fsub_rn(fmaf(beta, m, h), reset);
    }
    m2_out[e] = m;
    S2[e] = (m > 1.0f) ? 1.0f : 0.0f;
}

// ---------------------------------------------------------------------------
// Heads: value/action + leaky epilogues (FMA form). One block per row.
// ---------------------------------------------------------------------------
__global__ __launch_bounds__(256) void k_heads(
    const float* __restrict__ S2,
    const float* __restrict__ Wc, const float* __restrict__ bc,
    const float* __restrict__ Wa, const float* __restrict__ ba,
    const float* __restrict__ mem_act, const float* __restrict__ mem_crit,
    const float* __restrict__ beta_critp, const float* __restrict__ beta_actp,
    float* __restrict__ out)
{
    const int i = blockIdx.x;
    __shared__ float row[H_DIM];
    for (int h = threadIdx.x; h < H_DIM; h += blockDim.x)
        row[h] = S2[(size_t)i * H_DIM + h];
    __syncthreads();

    float acc[33];
#pragma unroll
    for (int a = 0; a < 33; a++) acc[a] = 0.0f;

    for (int h = threadIdx.x; h < H_DIM; h += blockDim.x) {
        float s = row[h];
        if (s != 0.0f) {
            acc[0] += Wc[h];
#pragma unroll
            for (int a = 0; a < 32; a++)
                acc[a + 1] += Wa[(size_t)a * H_DIM + h];
        }
    }

#pragma unroll
    for (int a = 0; a < 33; a++)
#pragma unroll
        for (int off = 16; off > 0; off >>= 1)
            acc[a] += __shfl_xor_sync(0xFFFFFFFFu, acc[a], off);

    __shared__ float part[8][33];
    const int wid = threadIdx.x >> 5, lane = threadIdx.x & 31;
    if (lane == 0) {
#pragma unroll
        for (int a = 0; a < 33; a++) part[wid][a] = acc[a];
    }
    __syncthreads();

    if (threadIdx.x < 33) {
        const int a = threadIdx.x;
        float y = 0.0f;
#pragma unroll
        for (int w = 0; w < 8; w++) y += part[w][a];
        if (a == 0) {
            y = __fadd_rn(y, bc[0]);
            const float beta = *beta_critp;
            float mem = mem_crit[i];
            float reset = (mem > 1.0f) ? 1.0f : 0.0f;
            float m = __fsub_rn(fmaf(beta, mem, y), reset);
            out[OFF_VALUE + i] = (m > 1.0f) ? 1.0f : 0.0f;
            out[OFF_MCRIT + i] = m;
        } else {
            const int j = a - 1;
            y = __fadd_rn(y, ba[j]);
            const float beta = *beta_actp;
            float mem = mem_act[(size_t)i * A_DIM + j];
            float reset = (mem > 1.0f) ? 1.0f : 0.0f;
            float m = __fsub_rn(fmaf(beta, mem, y), reset);
            out[OFF_ACTION + (size_t)i * A_DIM + j] = (m > 1.0f) ? 1.0f : 0.0f;
            out[OFF_MACT + (size_t)i * A_DIM + j] = m;
        }
    }
}

// ---------------------------------------------------------------------------
extern "C" void kernel_launch(void* const* d_in, const int* in_sizes, int n_in,
                              void* d_out, int out_size)
{
    const float* inputs   = (const float*)d_in[0];
    const float* mem1     = (const float*)d_in[1];
    const float* mem2     = (const float*)d_in[2];
    const float* mem_act  = (const float*)d_in[3];
    const float* mem_crit = (const float*)d_in[4];
    const float* W1 = (const float*)d_in[5];
    const float* b1 = (const float*)d_in[6];
    const float* W2 = (const float*)d_in[7];
    const float* b2 = (const float*)d_in[8];
    const float* Wc = (const float*)d_in[9];
    const float* bc = (const float*)d_in[10];
    const float* Wa = (const float*)d_in[11];
    const float* ba = (const float*)d_in[12];
    const float* beta1     = (const float*)d_in[13];
    const float* beta2     = (const float*)d_in[14];
    const float* beta_crit = (const float*)d_in[15];
    const float* beta_act  = (const float*)d_in[16];
    float* out = (float*)d_out;

    float *cur1, *S1, *Hb, *S2;
    cudaGetSymbolAddress((void**)&cur1, g_cur1);
    cudaGetSymbolAddress((void**)&S1, g_S1);
    cudaGetSymbolAddress((void**)&Hb, g_H);
    cudaGetSymbolAddress((void**)&S2, g_S2);

    // 1) cur1 = inputs @ W1^T + b1 (bit-exact path)
    sgemm_nt<<<dim3(H_DIM / 128, MROWS / 128), 256>>>(
        inputs, W1, b1, cur1, MROWS, H_DIM, S_DIM);

    // 2) m1 scan -> S1 spikes (bit-exact path)
    k_scan1<<<(unsigned)((NELEM + 255) / 256), 256>>>(
        cur1, mem1, beta1, out + OFF_M1, S1);

    // 3) fused big GEMM, 4-way K-sliced rounding: H = S1 @ W2^T + b2
    sgemm_split4_nt<<<dim3(H_DIM / 64, MBIG / 128), 256>>>(
        S1, W2, b2, Hb, MBIG, H_DIM, H_DIM);

    // 4) m2 scan -> m2 final, S2 spikes
    k_scan2<<<(unsigned)((NELEM + 255) / 256), 256>>>(
        Hb, mem2, beta2, out + OFF_M2, S2);

    // 5) heads
    k_heads<<<MROWS, 256>>>(S2, Wc, bc, Wa, ba, mem_act, mem_crit,
                            beta_crit, beta_act, out);
}

// round 6
// speedup vs baseline: 1.0324x; 1.0324x over previous
#include <cuda_runtime.h>
#include <cstddef>

// Problem dims
#define T_STEPS 16
#define B_DIM   64
#define S_DIM   512
#define H_DIM   2048
#define A_DIM   32
#define MROWS   (T_STEPS * B_DIM)          // 1024
#define NELEM   ((size_t)MROWS * H_DIM)    // 2,097,152
#define MBIG    (T_STEPS * MROWS)          // 16384

// Output layout: concat of (value, action, m1, m2, m_act, m_crit), fp32
#define OFF_VALUE  0
#define OFF_ACTION 1024
#define OFF_M1     33792
#define OFF_M2     2130944
#define OFF_MACT   4228096
#define OFF_MCRIT  4260864

// Scratch (device globals: allocation-free per harness rules)
__device__ float g_cur1[MROWS * H_DIM];                    // 8 MB
__device__ float g_S1[(size_t)T_STEPS * MROWS * H_DIM];    // 128 MB
__device__ float g_H[(size_t)T_STEPS * MROWS * H_DIM];     // 128 MB
__device__ float g_S2[MROWS * H_DIM];                      // 8 MB

// ---------------------------------------------------------------------------
// Packed f32x2 helpers (FFMA2: 2 independent rn FMAs per instruction;
// per-32-bit-lane rounding identical to scalar FFMA -> bit-exactness kept)
// ---------------------------------------------------------------------------
__device__ __forceinline__ unsigned long long pack2(float x, float y) {
    unsigned long long r;
    asm("mov.b64 %0, {%1, %2};" : "=l"(r) : "f"(x), "f"(y));
    return r;
}
__device__ __forceinline__ void fma2(unsigned long long& acc,
                                     unsigned long long a,
                                     unsigned long long b) {
    asm("fma.rn.f32x2 %0, %1, %2, %0;" : "+l"(acc) : "l"(a), "l"(b));
}
__device__ __forceinline__ void add2(unsigned long long& a,
                                     unsigned long long b) {
    asm("add.rn.f32x2 %0, %0, %1;" : "+l"(a) : "l"(b));
}
__device__ __forceinline__ float2 unpack2(unsigned long long v) {
    float2 f;
    asm("mov.b64 {%0, %1}, %2;" : "=f"(f.x), "=f"(f.y) : "l"(v));
    return f;
}

// ---------------------------------------------------------------------------
// NT SGEMM for cur1 (single accumulator chain, strictly ascending k) —
// rounding chain BIT-EXACT (proven m1=0); now issued as FFMA2 pairs over
// adjacent n-columns (per-lane rounding unchanged).
// BM=BN=128, BK=8, TM=8, TN=8(4 pairs), 256 threads.
// ---------------------------------------------------------------------------
__global__ __launch_bounds__(256) void sgemm_nt(
    const float* __restrict__ A, const float* __restrict__ B,
    const float* __restrict__ bias, float* __restrict__ C,
    int M, int N, int K)
{
    __shared__ float As[8][128];
    __shared__ float Bs[8][128];

    const int tid = threadIdx.x;
    const int bm = blockIdx.y * 128;
    const int bn = blockIdx.x * 128;

    const int lrow = tid >> 1;
    const int lcol = (tid & 1) * 4;

    const int tx = tid & 15;
    const int ty = tid >> 4;

    unsigned long long acc[8][4];
#pragma unroll
    for (int i = 0; i < 8; i++)
#pragma unroll
        for (int j = 0; j < 4; j++) acc[i][j] = 0ULL;

    const float* Aptr = A + (size_t)(bm + lrow) * K + lcol;
    const float* Bptr = B + (size_t)(bn + lrow) * K + lcol;

    for (int k0 = 0; k0 < K; k0 += 8) {
        float4 a4 = *(const float4*)(Aptr + k0);
        float4 b4 = *(const float4*)(Bptr + k0);
        As[lcol + 0][lrow] = a4.x; As[lcol + 1][lrow] = a4.y;
        As[lcol + 2][lrow] = a4.z; As[lcol + 3][lrow] = a4.w;
        Bs[lcol + 0][lrow] = b4.x; Bs[lcol + 1][lrow] = b4.y;
        Bs[lcol + 2][lrow] = b4.z; Bs[lcol + 3][lrow] = b4.w;
        __syncthreads();

#pragma unroll
        for (int k = 0; k < 8; k++) {
            float ar[8];
            float4 t;
            t = *(const float4*)&As[k][ty * 8];     ar[0]=t.x; ar[1]=t.y; ar[2]=t.z; ar[3]=t.w;
            t = *(const float4*)&As[k][ty * 8 + 4]; ar[4]=t.x; ar[5]=t.y; ar[6]=t.z; ar[7]=t.w;
            float4 b0 = *(const float4*)&Bs[k][tx * 8];
            float4 b1 = *(const float4*)&Bs[k][tx * 8 + 4];
            unsigned long long bp[4];
            bp[0] = pack2(b0.x, b0.y); bp[1] = pack2(b0.z, b0.w);
            bp[2] = pack2(b1.x, b1.y); bp[3] = pack2(b1.z, b1.w);
#pragma unroll
            for (int i = 0; i < 8; i++) {
                unsigned long long ap = pack2(ar[i], ar[i]);
#pragma unroll
                for (int j = 0; j < 4; j++)
                    fma2(acc[i][j], ap, bp[j]);
            }
        }
        __syncthreads();
    }

    const int row0 = bm + ty * 8;
    const int col0 = bn + tx * 8;
#pragma unroll
    for (int i = 0; i < 8; i++) {
#pragma unroll
        for (int jv = 0; jv < 2; jv++) {
            float2 p0 = unpack2(acc[i][jv * 2 + 0]);
            float2 p1 = unpack2(acc[i][jv * 2 + 1]);
            float4 v;
            v.x = __fadd_rn(p0.x, bias[col0 + jv * 4 + 0]);
            v.y = __fadd_rn(p0.y, bias[col0 + jv * 4 + 1]);
            v.z = __fadd_rn(p1.x, bias[col0 + jv * 4 + 2]);
            v.w = __fadd_rn(p1.y, bias[col0 + jv * 4 + 3]);
            *(float4*)(C + (size_t)(row0 + i) * N + col0 + jv * 4) = v;
        }
    }
}

// ---------------------------------------------------------------------------
// 4-way K-sliced NT SGEMM (reference's sliced1x4 rounding, PROVEN round 5):
// P_s = ascending FMA chain over k in [s*K/4,(s+1)*K/4);
// C = (((P0+P1)+P2)+P3) + bias.  Now with FFMA2 pairs (rounding unchanged).
// BM=128, BN=64, BK=16, TM=8, TN=4(2 pairs), 256 threads.
// ---------------------------------------------------------------------------
#define SPLIT_TILE_LOOP(KSTART, KEND, ACC)                                    \
    for (int k0 = (KSTART); k0 < (KEND); k0 += 16) {                          \
        {                                                                     \
            float4 a4 = *(const float4*)(Aptr + k0);                          \
            float4 a4b = *(const float4*)(Aptr + k0 + 4);                     \
            As[ak + 0][arow] = a4.x;  As[ak + 1][arow] = a4.y;                \
            As[ak + 2][arow] = a4.z;  As[ak + 3][arow] = a4.w;                \
            As[ak + 4][arow] = a4b.x; As[ak + 5][arow] = a4b.y;               \
            As[ak + 6][arow] = a4b.z; As[ak + 7][arow] = a4b.w;               \
            float4 b4 = *(const float4*)(Bptr + k0);                          \
            Bs[bk + 0][brow] = b4.x; Bs[bk + 1][brow] = b4.y;                 \
            Bs[bk + 2][brow] = b4.z; Bs[bk + 3][brow] = b4.w;                 \
        }                                                                     \
        __syncthreads();                                                      \
        _Pragma("unroll")                                                     \
        for (int k = 0; k < 16; k++) {                                        \
            float ar[8];                                                      \
            float4 t;                                                         \
            t = *(const float4*)&As[k][ty * 8];                               \
            ar[0]=t.x; ar[1]=t.y; ar[2]=t.z; ar[3]=t.w;                       \
            t = *(const float4*)&As[k][ty * 8 + 4];                           \
            ar[4]=t.x; ar[5]=t.y; ar[6]=t.z; ar[7]=t.w;                       \
            float4 b4 = *(const float4*)&Bs[k][tx * 4];                       \
            unsigned long long bp0 = pack2(b4.x, b4.y);                       \
            unsigned long long bp1 = pack2(b4.z, b4.w);                       \
            _Pragma("unroll")                                                 \
            for (int i = 0; i < 8; i++) {                                     \
                unsigned long long ap = pack2(ar[i], ar[i]);                  \
                fma2(ACC[i][0], ap, bp0);                                     \
                fma2(ACC[i][1], ap, bp1);                                     \
            }                                                                 \
        }                                                                     \
        __syncthreads();                                                      \
    }

__global__ __launch_bounds__(256) void sgemm_split4_nt(
    const float* __restrict__ A, const float* __restrict__ B,
    const float* __restrict__ bias, float* __restrict__ C,
    int M, int N, int K)
{
    __shared__ float As[16][128];
    __shared__ float Bs[16][64];

    const int tid = threadIdx.x;
    const int bm = blockIdx.y * 128;
    const int bn = blockIdx.x * 64;

    const int arow = tid >> 1;          // 0..127
    const int ak   = (tid & 1) * 8;     // 0 or 8
    const int brow = tid >> 2;          // 0..63
    const int bk   = (tid & 3) * 4;     // 0,4,8,12

    const int ty = tid >> 4;            // rows ty*8
    const int tx = tid & 15;            // cols tx*4

    unsigned long long accA[8][2], accB[8][2];
#pragma unroll
    for (int i = 0; i < 8; i++) { accA[i][0] = 0ULL; accA[i][1] = 0ULL; }

    const float* Aptr = A + (size_t)(bm + arow) * K + ak;
    const float* Bptr = B + (size_t)(bn + brow) * K + bk;

    const int Kq = K >> 2;   // slice length

    // slice 0 -> accA
    SPLIT_TILE_LOOP(0, Kq, accA)

    // slices 1..3 -> accB, fold serially: A = A + B
#pragma unroll 1
    for (int s = 1; s < 4; s++) {
#pragma unroll
        for (int i = 0; i < 8; i++) { accB[i][0] = 0ULL; accB[i][1] = 0ULL; }
        const int ks = s * Kq;
        const int ke = ks + Kq;
        SPLIT_TILE_LOOP(ks, ke, accB)
#pragma unroll
        for (int i = 0; i < 8; i++) {
            add2(accA[i][0], accB[i][0]);
            add2(accA[i][1], accB[i][1]);
        }
    }

    const int row0 = bm + ty * 8;
    const int col0 = bn + tx * 4;
#pragma unroll
    for (int i = 0; i < 8; i++) {
        float2 p0 = unpack2(accA[i][0]);
        float2 p1 = unpack2(accA[i][1]);
        float4 v;
        v.x = __fadd_rn(p0.x, bias[col0 + 0]);
        v.y = __fadd_rn(p0.y, bias[col0 + 1]);
        v.z = __fadd_rn(p1.x, bias[col0 + 2]);
        v.w = __fadd_rn(p1.y, bias[col0 + 3]);
        *(float4*)(C + (size_t)(row0 + i) * N + col0) = v;
    }
}

// ---------------------------------------------------------------------------
// m1 scan (BIT-EXACT — do not touch)
// ---------------------------------------------------------------------------
__global__ void k_scan1(const float* __restrict__ cur1,
                        const float* __restrict__ mem1,
                        const float* __restrict__ beta1p,
                        float* __restrict__ m1_out,
                        float* __restrict__ S1)
{
    size_t e = (size_t)blockIdx.x * blockDim.x + threadIdx.x;
    if (e >= NELEM) return;
    const float beta = *beta1p;
    const float c = cur1[e];
    float m = mem1[e];
#pragma unroll
    for (int k = 0; k < T_STEPS; k++) {
        float reset = (m > 1.0f) ? 1.0f : 0.0f;
        m = __fsub_rn(fmaf(beta, m, c), reset);
        S1[(size_t)k * NELEM + e] = (m > 1.0f) ? 1.0f : 0.0f;
    }
    m1_out[e] = m;
}

// ---------------------------------------------------------------------------
// m2 scan over precomputed h_k (b2 folded in by the GEMM), FMA form.
// ---------------------------------------------------------------------------
__global__ void k_scan2(const float* __restrict__ Hbuf,
                        const float* __restrict__ mem2,
                        const float* __restrict__ beta2p,
                        float* __restrict__ m2_out,
                        float* __restrict__ S2)
{
    size_t e = (size_t)blockIdx.x * blockDim.x + threadIdx.x;
    if (e >= NELEM) return;
    const float beta = *beta2p;
    float m = mem2[e];
#pragma unroll
    for (int k = 0; k < T_STEPS; k++) {
        float h = Hbuf[(size_t)k * NELEM + e];
        float reset = (m > 1.0f) ? 1.0f : 0.0f;
        m = __fsub_rn(fmaf(beta, m, h), reset);
    }
    m2_out[e] = m;
    S2[e] = (m > 1.0f) ? 1.0f : 0.0f;
}

// ---------------------------------------------------------------------------
// Heads: value/action + leaky epilogues (FMA form). One block per row.
// ---------------------------------------------------------------------------
__global__ __launch_bounds__(256) void k_heads(
    const float* __restrict__ S2,
    const float* __restrict__ Wc, const float* __restrict__ bc,
    const float* __restrict__ Wa, const float* __restrict__ ba,
    const float* __restrict__ mem_act, const float* __restrict__ mem_crit,
    const float* __restrict__ beta_critp, const float* __restrict__ beta_actp,
    float* __restrict__ out)
{
    const int i = blockIdx.x;
    __shared__ float row[H_DIM];
    for (int h = threadIdx.x; h < H_DIM; h += blockDim.x)
        row[h] = S2[(size_t)i * H_DIM + h];
    __syncthreads();

    float acc[33];
#pragma unroll
    for (int a = 0; a < 33; a++) acc[a] = 0.0f;

    for (int h = threadIdx.x; h < H_DIM; h += blockDim.x) {
        float s = row[h];
        if (s != 0.0f) {
            acc[0] += Wc[h];
#pragma unroll
            for (int a = 0; a < 32; a++)
                acc[a + 1] += Wa[(size_t)a * H_DIM + h];
        }
    }

#pragma unroll
    for (int a = 0; a < 33; a++)
#pragma unroll
        for (int off = 16; off > 0; off >>= 1)
            acc[a] += __shfl_xor_sync(0xFFFFFFFFu, acc[a], off);

    __shared__ float part[8][33];
    const int wid = threadIdx.x >> 5, lane = threadIdx.x & 31;
    if (lane == 0) {
#pragma unroll
        for (int a = 0; a < 33; a++) part[wid][a] = acc[a];
    }
    __syncthreads();

    if (threadIdx.x < 33) {
        const int a = threadIdx.x;
        float y = 0.0f;
#pragma unroll
        for (int w = 0; w < 8; w++) y += part[w][a];
        if (a == 0) {
            y = __fadd_rn(y, bc[0]);
            const float beta = *beta_critp;
            float mem = mem_crit[i];
            float reset = (mem > 1.0f) ? 1.0f : 0.0f;
            float m = __fsub_rn(fmaf(beta, mem, y), reset);
            out[OFF_VALUE + i] = (m > 1.0f) ? 1.0f : 0.0f;
            out[OFF_MCRIT + i] = m;
        } else {
            const int j = a - 1;
            y = __fadd_rn(y, ba[j]);
            const float beta = *beta_actp;
            float mem = mem_act[(size_t)i * A_DIM + j];
            float reset = (mem > 1.0f) ? 1.0f : 0.0f;
            float m = __fsub_rn(fmaf(beta, mem, y), reset);
            out[OFF_ACTION + (size_t)i * A_DIM + j] = (m > 1.0f) ? 1.0f : 0.0f;
            out[OFF_MACT + (size_t)i * A_DIM + j] = m;
        }
    }
}

// ---------------------------------------------------------------------------
extern "C" void kernel_launch(void* const* d_in, const int* in_sizes, int n_in,
                              void* d_out, int out_size)
{
    const float* inputs   = (const float*)d_in[0];
    const float* mem1     = (const float*)d_in[1];
    const float* mem2     = (const float*)d_in[2];
    const float* mem_act  = (const float*)d_in[3];
    const float* mem_crit = (const float*)d_in[4];
    const float* W1 = (const float*)d_in[5];
    const float* b1 = (const float*)d_in[6];
    const float* W2 = (const float*)d_in[7];
    const float* b2 = (const float*)d_in[8];
    const float* Wc = (const float*)d_in[9];
    const float* bc = (const float*)d_in[10];
    const float* Wa = (const float*)d_in[11];
    const float* ba = (const float*)d_in[12];
    const float* beta1     = (const float*)d_in[13];
    const float* beta2     = (const float*)d_in[14];
    const float* beta_crit = (const float*)d_in[15];
    const float* beta_act  = (const float*)d_in[16];
    float* out = (float*)d_out;

    float *cur1, *S1, *Hb, *S2;
    cudaGetSymbolAddress((void**)&cur1, g_cur1);
    cudaGetSymbolAddress((void**)&S1, g_S1);
    cudaGetSymbolAddress((void**)&Hb, g_H);
    cudaGetSymbolAddress((void**)&S2, g_S2);

    // 1) cur1 = inputs @ W1^T + b1 (bit-exact chain, FFMA2 issue)
    sgemm_nt<<<dim3(H_DIM / 128, MROWS / 128), 256>>>(
        inputs, W1, b1, cur1, MROWS, H_DIM, S_DIM);

    // 2) m1 scan -> S1 spikes (bit-exact path)
    k_scan1<<<(unsigned)((NELEM + 255) / 256), 256>>>(
        cur1, mem1, beta1, out + OFF_M1, S1);

    // 3) fused big GEMM, sliced1x4 rounding, FFMA2: H = S1 @ W2^T + b2
    sgemm_split4_nt<<<dim3(H_DIM / 64, MBIG / 128), 256>>>(
        S1, W2, b2, Hb, MBIG, H_DIM, H_DIM);

    // 4) m2 scan -> m2 final, S2 spikes
    k_scan2<<<(unsigned)((NELEM + 255) / 256), 256>>>(
        Hb, mem2, beta2, out + OFF_M2, S2);

    // 5) heads
    k_heads<<<MROWS, 256>>>(S2, Wc, bc, Wa, ba, mem_act, mem_crit,
                            beta_crit, beta_act, out);
}